// round 1
// baseline (speedup 1.0000x reference)
#include <cuda_runtime.h>
#include <math.h>

#define BB 64
#define HH 1024
#define INN 1024
#define GN_EPS 1e-5f

// Scratch (no allocations allowed): gates q,k,v,i,f,o ; h_tilde_raw ; per-batch scalars
__device__ float g_gate[6][BB * HH];
__device__ float g_ht[BB * HH];
__device__ float g_denom[BB];
__device__ float g_vq[BB];

__device__ __forceinline__ float sigmoidf_(float x) {
    return 1.0f / (1.0f + expf(-x));
}
__device__ __forceinline__ float softplusf_(float x) {
    // stable: max(x,0) + log1p(exp(-|x|))
    return fmaxf(x, 0.0f) + log1pf(expf(-fabsf(x)));
}

// ----------------------------------------------------------------------------
// Kernel 1: six fused GEMMs  y[g][b][h] = act( sum_k x[b][k] * W_g[h][k] + b_g[h] )
// grid = (H/64, 6), block = 256 (16x16), tile M=64(all B) x N=64, Kc=16, 4x4 microtile
// ----------------------------------------------------------------------------
__global__ __launch_bounds__(256) void k1_gemm_gates(
    const float* __restrict__ x,
    const float* __restrict__ Wq, const float* __restrict__ Wk,
    const float* __restrict__ Wv, const float* __restrict__ Wi,
    const float* __restrict__ Wf, const float* __restrict__ Wo,
    const float* __restrict__ bi, const float* __restrict__ bf,
    const float* __restrict__ bo)
{
    const int g = blockIdx.y;
    const float* __restrict__ W =
        (g == 0) ? Wq : (g == 1) ? Wk : (g == 2) ? Wv : (g == 3) ? Wi : (g == 4) ? Wf : Wo;
    const float* __restrict__ bias =
        (g == 3) ? bi : (g == 4) ? bf : (g == 5) ? bo : nullptr;

    __shared__ float Xs[16][68];  // [k][m], 68-float row stride keeps 16B alignment
    __shared__ float Ws[16][68];  // [k][n]

    const int tid = threadIdx.x;
    const int tx = tid & 15;   // n micro-group
    const int ty = tid >> 4;   // m micro-group
    const int n0 = blockIdx.x * 64;

    const int lm = tid >> 2;         // 0..63 loading row
    const int lk = (tid & 3) * 4;    // 0,4,8,12 loading k-offset

    float acc[4][4];
#pragma unroll
    for (int i = 0; i < 4; i++)
#pragma unroll
        for (int j = 0; j < 4; j++) acc[i][j] = 0.0f;

    for (int k0 = 0; k0 < INN; k0 += 16) {
        float4 xa = *(const float4*)(x + lm * INN + k0 + lk);
        float4 wa = *(const float4*)(W + (size_t)(n0 + lm) * INN + k0 + lk);
        __syncthreads();
        Xs[lk + 0][lm] = xa.x; Xs[lk + 1][lm] = xa.y;
        Xs[lk + 2][lm] = xa.z; Xs[lk + 3][lm] = xa.w;
        Ws[lk + 0][lm] = wa.x; Ws[lk + 1][lm] = wa.y;
        Ws[lk + 2][lm] = wa.z; Ws[lk + 3][lm] = wa.w;
        __syncthreads();
#pragma unroll
        for (int kk = 0; kk < 16; kk++) {
            float4 a = *(const float4*)&Xs[kk][ty * 4];
            float4 b = *(const float4*)&Ws[kk][tx * 4];
            float av[4] = {a.x, a.y, a.z, a.w};
            float bv[4] = {b.x, b.y, b.z, b.w};
#pragma unroll
            for (int i = 0; i < 4; i++)
#pragma unroll
                for (int j = 0; j < 4; j++)
                    acc[i][j] = fmaf(av[i], bv[j], acc[i][j]);
        }
    }

    float bvals[4] = {0.f, 0.f, 0.f, 0.f};
    if (bias) {
#pragma unroll
        for (int j = 0; j < 4; j++) bvals[j] = bias[n0 + tx * 4 + j];
    }

    float* __restrict__ outg = g_gate[g];
#pragma unroll
    for (int i = 0; i < 4; i++) {
        const int m = ty * 4 + i;
        float v[4];
#pragma unroll
        for (int j = 0; j < 4; j++) {
            float y = acc[i][j] + bvals[j];
            if (g == 3)       y = softplusf_(y);
            else if (g >= 4)  y = sigmoidf_(y);
            v[j] = y;
        }
        float4 o4 = make_float4(v[0], v[1], v[2], v[3]);
        *(float4*)(outg + m * HH + n0 + tx * 4) = o4;
    }
}

// ----------------------------------------------------------------------------
// Kernel 2: n = f*n_prev + i*k ; m = max(f*m_prev, i) ;
//           denom[b] = max(sum_h n*q, 1) ; vq[b] = sum_h v*q
// grid = 64 (one block per batch), block = 256
// ----------------------------------------------------------------------------
__global__ __launch_bounds__(256) void k2_nm_reduce(
    const float* __restrict__ n_prev, const float* __restrict__ m_prev,
    float* __restrict__ out_n, float* __restrict__ out_m)
{
    const int b = blockIdx.x;
    const int tid = threadIdx.x;
    const int base = b * HH;

    float snq = 0.0f, svq = 0.0f;
#pragma unroll
    for (int j = 0; j < 4; j++) {
        const int h = tid + j * 256;
        const float qv = g_gate[0][base + h];
        const float kv = g_gate[1][base + h];
        const float vv = g_gate[2][base + h];
        const float iv = g_gate[3][base + h];
        const float fv = g_gate[4][base + h];
        const float nv = fmaf(fv, n_prev[base + h], iv * kv);
        const float mv = fmaxf(fv * m_prev[base + h], iv);
        out_n[base + h] = nv;
        out_m[base + h] = mv;
        snq = fmaf(nv, qv, snq);
        svq = fmaf(vv, qv, svq);
    }

    __shared__ float s1[256], s2[256];
    s1[tid] = snq; s2[tid] = svq;
    __syncthreads();
    for (int s = 128; s > 0; s >>= 1) {
        if (tid < s) { s1[tid] += s1[tid + s]; s2[tid] += s2[tid + s]; }
        __syncthreads();
    }
    if (tid == 0) {
        g_denom[b] = fmaxf(s1[0], 1.0f);
        g_vq[b] = s2[0];
    }
}

// ----------------------------------------------------------------------------
// Kernel 3: THE streaming kernel (512 MB):
//   C[b,r,c] = f_r * C_prev[b,r,c] + (i_r*k_r) * v_c
//   ht_raw[b,r] = f_r * <C_prev[b,r,:], q> + (i_r*k_r) * vq[b]
// grid = (128 rowblocks, 64 b), block = 256 (8 warps, 1 warp per row)
// ----------------------------------------------------------------------------
__global__ __launch_bounds__(256) void k3_c_update(
    const float* __restrict__ C_prev, float* __restrict__ out_C)
{
    const int b = blockIdx.y;
    const int r0 = blockIdx.x * 8;
    const int tid = threadIdx.x;

    __shared__ float sq[HH];
    __shared__ float sv[HH];
#pragma unroll
    for (int j = 0; j < 4; j++) {
        const int idx = tid + j * 256;
        sq[idx] = g_gate[0][b * HH + idx];
        sv[idx] = g_gate[2][b * HH + idx];
    }
    __syncthreads();

    const int warp = tid >> 5;
    const int lane = tid & 31;
    const int r = r0 + warp;

    const float f  = g_gate[4][b * HH + r];
    const float ik = g_gate[3][b * HH + r] * g_gate[1][b * HH + r];

    const float* __restrict__ cp = C_prev + ((size_t)b * HH + r) * HH;
    float* __restrict__ co = out_C + ((size_t)b * HH + r) * HH;

    float dot = 0.0f;
#pragma unroll
    for (int j = 0; j < 8; j++) {
        const int c = lane * 4 + j * 128;
        float4 p  = *(const float4*)(cp + c);
        float4 vv = *(const float4*)(sv + c);
        float4 qq = *(const float4*)(sq + c);
        float4 o;
        o.x = fmaf(f, p.x, ik * vv.x);
        o.y = fmaf(f, p.y, ik * vv.y);
        o.z = fmaf(f, p.z, ik * vv.z);
        o.w = fmaf(f, p.w, ik * vv.w);
        *(float4*)(co + c) = o;
        dot = fmaf(p.x, qq.x, dot);
        dot = fmaf(p.y, qq.y, dot);
        dot = fmaf(p.z, qq.z, dot);
        dot = fmaf(p.w, qq.w, dot);
    }
#pragma unroll
    for (int s = 16; s > 0; s >>= 1)
        dot += __shfl_xor_sync(0xFFFFFFFFu, dot, s);
    if (lane == 0)
        g_ht[b * HH + r] = fmaf(f, dot, ik * g_vq[b]);
}

// ----------------------------------------------------------------------------
// Kernel 4: h_tilde = ht_raw/denom ; GroupNorm(1 group) over H ; h = o * norm
// grid = 64 (one block per batch), block = 256
// ----------------------------------------------------------------------------
__global__ __launch_bounds__(256) void k4_groupnorm(
    const float* __restrict__ gn_w, const float* __restrict__ gn_b,
    float* __restrict__ out_h)
{
    const int b = blockIdx.x;
    const int tid = threadIdx.x;
    const int base = b * HH;
    const float inv_d = 1.0f / g_denom[b];

    float xs[4];
    float s = 0.0f, s2 = 0.0f;
#pragma unroll
    for (int j = 0; j < 4; j++) {
        const int h = tid + j * 256;
        const float xv = g_ht[base + h] * inv_d;
        xs[j] = xv;
        s += xv;
        s2 = fmaf(xv, xv, s2);
    }

    __shared__ float r1[256], r2[256];
    __shared__ float mu_s, rstd_s;
    r1[tid] = s; r2[tid] = s2;
    __syncthreads();
    for (int st = 128; st > 0; st >>= 1) {
        if (tid < st) { r1[tid] += r1[tid + st]; r2[tid] += r2[tid + st]; }
        __syncthreads();
    }
    if (tid == 0) {
        const float mu = r1[0] * (1.0f / HH);
        float var = r2[0] * (1.0f / HH) - mu * mu;
        var = fmaxf(var, 0.0f);
        mu_s = mu;
        rstd_s = rsqrtf(var + GN_EPS);
    }
    __syncthreads();
    const float mu = mu_s, rstd = rstd_s;

#pragma unroll
    for (int j = 0; j < 4; j++) {
        const int h = tid + j * 256;
        const float ov = g_gate[5][base + h];
        const float norm = fmaf((xs[j] - mu) * rstd, gn_w[h], gn_b[h]);
        out_h[base + h] = ov * norm;
    }
}

// ----------------------------------------------------------------------------
extern "C" void kernel_launch(void* const* d_in, const int* in_sizes, int n_in,
                              void* d_out, int out_size)
{
    const float* x      = (const float*)d_in[0];
    const float* C_prev = (const float*)d_in[1];
    const float* n_prev = (const float*)d_in[2];
    const float* m_prev = (const float*)d_in[3];
    const float* Wq     = (const float*)d_in[4];
    const float* Wk     = (const float*)d_in[5];
    const float* Wv     = (const float*)d_in[6];
    const float* Wi     = (const float*)d_in[7];
    const float* bi     = (const float*)d_in[8];
    const float* Wf     = (const float*)d_in[9];
    const float* bf     = (const float*)d_in[10];
    const float* Wo     = (const float*)d_in[11];
    const float* bo     = (const float*)d_in[12];
    const float* gn_w   = (const float*)d_in[13];
    const float* gn_b   = (const float*)d_in[14];

    float* out   = (float*)d_out;
    float* out_h = out;                                   // [B,H]
    float* out_C = out_h + BB * HH;                       // [B,H,H]
    float* out_n = out_C + (size_t)BB * HH * HH;          // [B,H]
    float* out_m = out_n + BB * HH;                       // [B,H]

    dim3 g1(HH / 64, 6);
    k1_gemm_gates<<<g1, 256>>>(x, Wq, Wk, Wv, Wi, Wf, Wo, bi, bf, bo);
    k2_nm_reduce<<<BB, 256>>>(n_prev, m_prev, out_n, out_m);
    dim3 g3(HH / 8, BB);
    k3_c_update<<<g3, 256>>>(C_prev, out_C);
    k4_groupnorm<<<BB, 256>>>(gn_w, gn_b, out_h);
}

// round 2
// speedup vs baseline: 1.2014x; 1.2014x over previous
#include <cuda_runtime.h>
#include <math.h>

#define BB 64
#define HH 1024
#define INN 1024
#define GN_EPS 1e-5f

// Scratch: gates q,k,v,i,f,o ; h_tilde_raw ; per-batch scalars
__device__ float g_gate[6][BB * HH];
__device__ float g_ht[BB * HH];
__device__ float g_denom[BB];
__device__ float g_vq[BB];

__device__ __forceinline__ float sigmoidf_(float x) {
    return 1.0f / (1.0f + expf(-x));
}
__device__ __forceinline__ float softplusf_(float x) {
    return fmaxf(x, 0.0f) + log1pf(expf(-fabsf(x)));
}

// ----------------------------------------------------------------------------
// Kernel 1: six fused GEMMs  y[g][b][h] = act( x @ W_g^T + b_g )
// Tile: M=64 (all batch) x N=16, Kc=32. grid=(64,6)=384 blocks, 128 threads.
// Microtile 4(m) x 2(n). Worst-SM serialization: 3 blocks.
// ----------------------------------------------------------------------------
#define K1N 16
#define K1KC 32

__global__ __launch_bounds__(128) void k1_gemm_gates(
    const float* __restrict__ x,
    const float* __restrict__ Wq, const float* __restrict__ Wk,
    const float* __restrict__ Wv, const float* __restrict__ Wi,
    const float* __restrict__ Wf, const float* __restrict__ Wo,
    const float* __restrict__ bi, const float* __restrict__ bf,
    const float* __restrict__ bo)
{
    const int g = blockIdx.y;
    const float* __restrict__ W =
        (g == 0) ? Wq : (g == 1) ? Wk : (g == 2) ? Wv : (g == 3) ? Wi : (g == 4) ? Wf : Wo;
    const float* __restrict__ bias =
        (g == 3) ? bi : (g == 4) ? bf : (g == 5) ? bo : nullptr;

    __shared__ float Xs[K1KC][68];   // [k][m], stride 68 keeps float4 alignment
    __shared__ float Ws[K1KC][20];   // [k][n]

    const int tid = threadIdx.x;
    const int tx = tid & 7;    // n micro-group (0..7), 2 cols each
    const int ty = tid >> 3;   // m micro-group (0..15), 4 rows each
    const int n0 = blockIdx.x * K1N;

    // W loader indices: 16 n-rows x 8 float4-chunks = 128 chunks, 1/thread
    const int wrow = tid >> 3;        // 0..15
    const int wkq = (tid & 7) * 4;    // 0..28

    float acc[4][2];
#pragma unroll
    for (int i = 0; i < 4; i++) { acc[i][0] = 0.0f; acc[i][1] = 0.0f; }

    for (int k0 = 0; k0 < INN; k0 += K1KC) {
        // X tile: 64 rows x 8 chunks = 512 float4, 4 per thread
        float4 xa[4];
#pragma unroll
        for (int i = 0; i < 4; i++) {
            const int c = tid + i * 128;
            const int xr = c >> 3;
            const int xk = (c & 7) * 4;
            xa[i] = *(const float4*)(x + xr * INN + k0 + xk);
        }
        float4 wa = *(const float4*)(W + (size_t)(n0 + wrow) * INN + k0 + wkq);

        __syncthreads();
#pragma unroll
        for (int i = 0; i < 4; i++) {
            const int c = tid + i * 128;
            const int xr = c >> 3;
            const int xk = (c & 7) * 4;
            Xs[xk + 0][xr] = xa[i].x; Xs[xk + 1][xr] = xa[i].y;
            Xs[xk + 2][xr] = xa[i].z; Xs[xk + 3][xr] = xa[i].w;
        }
        Ws[wkq + 0][wrow] = wa.x; Ws[wkq + 1][wrow] = wa.y;
        Ws[wkq + 2][wrow] = wa.z; Ws[wkq + 3][wrow] = wa.w;
        __syncthreads();

#pragma unroll
        for (int kk = 0; kk < K1KC; kk++) {
            float4 a = *(const float4*)&Xs[kk][ty * 4];
            float2 b = *(const float2*)&Ws[kk][tx * 2];
            acc[0][0] = fmaf(a.x, b.x, acc[0][0]);
            acc[0][1] = fmaf(a.x, b.y, acc[0][1]);
            acc[1][0] = fmaf(a.y, b.x, acc[1][0]);
            acc[1][1] = fmaf(a.y, b.y, acc[1][1]);
            acc[2][0] = fmaf(a.z, b.x, acc[2][0]);
            acc[2][1] = fmaf(a.z, b.y, acc[2][1]);
            acc[3][0] = fmaf(a.w, b.x, acc[3][0]);
            acc[3][1] = fmaf(a.w, b.y, acc[3][1]);
        }
    }

    float b0 = 0.f, b1 = 0.f;
    if (bias) {
        b0 = bias[n0 + tx * 2 + 0];
        b1 = bias[n0 + tx * 2 + 1];
    }

    float* __restrict__ outg = g_gate[g];
#pragma unroll
    for (int i = 0; i < 4; i++) {
        const int m = ty * 4 + i;
        float y0 = acc[i][0] + b0;
        float y1 = acc[i][1] + b1;
        if (g == 3)      { y0 = softplusf_(y0); y1 = softplusf_(y1); }
        else if (g >= 4) { y0 = sigmoidf_(y0);  y1 = sigmoidf_(y1);  }
        *(float2*)(outg + m * HH + n0 + tx * 2) = make_float2(y0, y1);
    }
}

// ----------------------------------------------------------------------------
// Kernel 2: n = f*n_prev + i*k ; m = max(f*m_prev, i) ;
//           denom[b] = max(sum_h n*q, 1) ; vq[b] = sum_h v*q
// grid = 64, block = 1024, 1 element/thread, warp-shuffle 2-stage reduce
// ----------------------------------------------------------------------------
__global__ __launch_bounds__(1024) void k2_nm_reduce(
    const float* __restrict__ n_prev, const float* __restrict__ m_prev,
    float* __restrict__ out_n, float* __restrict__ out_m)
{
    const int b = blockIdx.x;
    const int tid = threadIdx.x;
    const int h = b * HH + tid;

    const float qv = g_gate[0][h];
    const float kv = g_gate[1][h];
    const float vv = g_gate[2][h];
    const float iv = g_gate[3][h];
    const float fv = g_gate[4][h];
    const float nv = fmaf(fv, n_prev[h], iv * kv);
    const float mv = fmaxf(fv * m_prev[h], iv);
    out_n[h] = nv;
    out_m[h] = mv;

    float snq = nv * qv;
    float svq = vv * qv;
#pragma unroll
    for (int s = 16; s > 0; s >>= 1) {
        snq += __shfl_xor_sync(0xFFFFFFFFu, snq, s);
        svq += __shfl_xor_sync(0xFFFFFFFFu, svq, s);
    }
    __shared__ float p1[32], p2[32];
    const int warp = tid >> 5, lane = tid & 31;
    if (lane == 0) { p1[warp] = snq; p2[warp] = svq; }
    __syncthreads();
    if (warp == 0) {
        float a = p1[lane], c = p2[lane];
#pragma unroll
        for (int s = 16; s > 0; s >>= 1) {
            a += __shfl_xor_sync(0xFFFFFFFFu, a, s);
            c += __shfl_xor_sync(0xFFFFFFFFu, c, s);
        }
        if (lane == 0) {
            g_denom[b] = fmaxf(a, 1.0f);
            g_vq[b] = c;
        }
    }
}

// ----------------------------------------------------------------------------
// Kernel 3: streaming 512 MB:
//   C[b,r,c] = f_r * C_prev[b,r,c] + (i_r*k_r) * v_c
//   ht_raw[b,r] = f_r * <C_prev[b,r,:], q> + (i_r*k_r) * vq[b]
// grid = (64 rowblocks, 64 b), block = 512 (16 warps, 1 warp/row)
// ----------------------------------------------------------------------------
__global__ __launch_bounds__(512) void k3_c_update(
    const float* __restrict__ C_prev, float* __restrict__ out_C)
{
    const int b = blockIdx.y;
    const int r0 = blockIdx.x * 16;
    const int tid = threadIdx.x;

    __shared__ float sq[HH];
    __shared__ float sv[HH];
#pragma unroll
    for (int j = 0; j < 2; j++) {
        const int idx = tid + j * 512;
        sq[idx] = g_gate[0][b * HH + idx];
        sv[idx] = g_gate[2][b * HH + idx];
    }
    __syncthreads();

    const int warp = tid >> 5;
    const int lane = tid & 31;
    const int r = r0 + warp;

    const float f  = g_gate[4][b * HH + r];
    const float ik = g_gate[3][b * HH + r] * g_gate[1][b * HH + r];

    const float* __restrict__ cp = C_prev + ((size_t)b * HH + r) * HH;
    float* __restrict__ co = out_C + ((size_t)b * HH + r) * HH;

    float dot = 0.0f;
#pragma unroll
    for (int j = 0; j < 8; j++) {
        const int c = lane * 4 + j * 128;
        float4 p  = __ldcs((const float4*)(cp + c));
        float4 vv = *(const float4*)(sv + c);
        float4 qq = *(const float4*)(sq + c);
        float4 o;
        o.x = fmaf(f, p.x, ik * vv.x);
        o.y = fmaf(f, p.y, ik * vv.y);
        o.z = fmaf(f, p.z, ik * vv.z);
        o.w = fmaf(f, p.w, ik * vv.w);
        __stcs((float4*)(co + c), o);
        dot = fmaf(p.x, qq.x, dot);
        dot = fmaf(p.y, qq.y, dot);
        dot = fmaf(p.z, qq.z, dot);
        dot = fmaf(p.w, qq.w, dot);
    }
#pragma unroll
    for (int s = 16; s > 0; s >>= 1)
        dot += __shfl_xor_sync(0xFFFFFFFFu, dot, s);
    if (lane == 0)
        g_ht[b * HH + r] = fmaf(f, dot, ik * g_vq[b]);
}

// ----------------------------------------------------------------------------
// Kernel 4: h_tilde = ht_raw/denom ; GroupNorm(1 group) ; h = o * norm
// grid = 64, block = 1024, warp-shuffle 2-stage reduce
// ----------------------------------------------------------------------------
__global__ __launch_bounds__(1024) void k4_groupnorm(
    const float* __restrict__ gn_w, const float* __restrict__ gn_b,
    float* __restrict__ out_h)
{
    const int b = blockIdx.x;
    const int tid = threadIdx.x;
    const int h = b * HH + tid;
    const float inv_d = 1.0f / g_denom[b];

    const float xv = g_ht[h] * inv_d;
    float s = xv, s2 = xv * xv;
#pragma unroll
    for (int st = 16; st > 0; st >>= 1) {
        s  += __shfl_xor_sync(0xFFFFFFFFu, s, st);
        s2 += __shfl_xor_sync(0xFFFFFFFFu, s2, st);
    }
    __shared__ float p1[32], p2[32];
    __shared__ float mu_s, rstd_s;
    const int warp = tid >> 5, lane = tid & 31;
    if (lane == 0) { p1[warp] = s; p2[warp] = s2; }
    __syncthreads();
    if (warp == 0) {
        float a = p1[lane], c = p2[lane];
#pragma unroll
        for (int st = 16; st > 0; st >>= 1) {
            a += __shfl_xor_sync(0xFFFFFFFFu, a, st);
            c += __shfl_xor_sync(0xFFFFFFFFu, c, st);
        }
        if (lane == 0) {
            const float mu = a * (1.0f / HH);
            float var = c * (1.0f / HH) - mu * mu;
            var = fmaxf(var, 0.0f);
            mu_s = mu;
            rstd_s = rsqrtf(var + GN_EPS);
        }
    }
    __syncthreads();

    const float norm = fmaf((xv - mu_s) * rstd_s, gn_w[tid], gn_b[tid]);
    out_h[h] = g_gate[5][h] * norm;
}

// ----------------------------------------------------------------------------
extern "C" void kernel_launch(void* const* d_in, const int* in_sizes, int n_in,
                              void* d_out, int out_size)
{
    const float* x      = (const float*)d_in[0];
    const float* C_prev = (const float*)d_in[1];
    const float* n_prev = (const float*)d_in[2];
    const float* m_prev = (const float*)d_in[3];
    const float* Wq     = (const float*)d_in[4];
    const float* Wk     = (const float*)d_in[5];
    const float* Wv     = (const float*)d_in[6];
    const float* Wi     = (const float*)d_in[7];
    const float* bi     = (const float*)d_in[8];
    const float* Wf     = (const float*)d_in[9];
    const float* bf     = (const float*)d_in[10];
    const float* Wo     = (const float*)d_in[11];
    const float* bo     = (const float*)d_in[12];
    const float* gn_w   = (const float*)d_in[13];
    const float* gn_b   = (const float*)d_in[14];

    float* out   = (float*)d_out;
    float* out_h = out;                                   // [B,H]
    float* out_C = out_h + BB * HH;                       // [B,H,H]
    float* out_n = out_C + (size_t)BB * HH * HH;          // [B,H]
    float* out_m = out_n + BB * HH;                       // [B,H]

    dim3 g1(HH / K1N, 6);
    k1_gemm_gates<<<g1, 128>>>(x, Wq, Wk, Wv, Wi, Wf, Wo, bi, bf, bo);
    k2_nm_reduce<<<BB, 1024>>>(n_prev, m_prev, out_n, out_m);
    dim3 g3(HH / 16, BB);
    k3_c_update<<<g3, 512>>>(C_prev, out_C);
    k4_groupnorm<<<BB, 1024>>>(gn_w, gn_b, out_h);
}

// round 3
// speedup vs baseline: 1.2266x; 1.0210x over previous
#include <cuda_runtime.h>
#include <math.h>

#define BB 64
#define HH 1024
#define INN 1024
#define GN_EPS 1e-5f

// Scratch: gates q,k,v,i,f,o ; h_tilde_raw ; per-batch scalars ; epilogue counters
__device__ float g_gate[6][BB * HH];
__device__ float g_ht[BB * HH];
__device__ float g_denom[BB];
__device__ float g_vq[BB];
__device__ unsigned int g_cnt[BB];   // zero-init; self-resetting

__device__ __forceinline__ float sigmoidf_(float x) {
    return 1.0f / (1.0f + expf(-x));
}
__device__ __forceinline__ float softplusf_(float x) {
    return fmaxf(x, 0.0f) + log1pf(expf(-fabsf(x)));
}

// ---- packed f32x2 helpers (sm_103a dual-rate fp32) ----
__device__ __forceinline__ unsigned long long dup2_(float v) {
    unsigned long long r;
    asm("mov.b64 %0, {%1, %1};" : "=l"(r) : "r"(__float_as_uint(v)));
    return r;
}
__device__ __forceinline__ void fma2_(unsigned long long& d,
                                      unsigned long long a,
                                      unsigned long long b) {
    asm("fma.rn.f32x2 %0, %1, %2, %0;" : "+l"(d) : "l"(a), "l"(b));
}
__device__ __forceinline__ float2 unpk_(unsigned long long v) {
    unsigned int lo, hi;
    asm("mov.b64 {%0, %1}, %2;" : "=r"(lo), "=r"(hi) : "l"(v));
    return make_float2(__uint_as_float(lo), __uint_as_float(hi));
}

// ----------------------------------------------------------------------------
// Kernel 1: six fused GEMMs  y[g][b][h] = act( x @ W_g^T + b_g )
// Tile M=64 x N=16, Kc=32, 128 threads, micro 4m x 2n, f32x2 packed FMA.
// ----------------------------------------------------------------------------
#define K1N 16
#define K1KC 32

__global__ __launch_bounds__(128) void k1_gemm_gates(
    const float* __restrict__ x,
    const float* __restrict__ Wq, const float* __restrict__ Wk,
    const float* __restrict__ Wv, const float* __restrict__ Wi,
    const float* __restrict__ Wf, const float* __restrict__ Wo,
    const float* __restrict__ bi, const float* __restrict__ bf,
    const float* __restrict__ bo)
{
    const int g = blockIdx.y;
    const float* __restrict__ W =
        (g == 0) ? Wq : (g == 1) ? Wk : (g == 2) ? Wv : (g == 3) ? Wi : (g == 4) ? Wf : Wo;
    const float* __restrict__ bias =
        (g == 3) ? bi : (g == 4) ? bf : (g == 5) ? bo : nullptr;

    __shared__ __align__(16) float Xs[K1KC][68];   // [k][m], stride 68 (272B, 16B-mult)
    __shared__ __align__(16) float Ws[K1KC][20];   // [k][n], stride 20 (80B, 8B-mult)

    const int tid = threadIdx.x;
    const int tx = tid & 7;    // n micro-group (0..7), 2 cols each
    const int ty = tid >> 3;   // m micro-group (0..15), 4 rows each
    const int n0 = blockIdx.x * K1N;

    const int wrow = tid >> 3;        // 0..15
    const int wkq = (tid & 7) * 4;    // 0..28

    // packed accumulators: acc[mi][nj] holds (m(2mi), m(2mi+1)) for col nj
    unsigned long long acc00 = 0ull, acc10 = 0ull, acc01 = 0ull, acc11 = 0ull;

    for (int k0 = 0; k0 < INN; k0 += K1KC) {
        float4 xa[4];
#pragma unroll
        for (int i = 0; i < 4; i++) {
            const int c = tid + i * 128;
            const int xr = c >> 3;
            const int xk = (c & 7) * 4;
            xa[i] = *(const float4*)(x + xr * INN + k0 + xk);
        }
        float4 wa = *(const float4*)(W + (size_t)(n0 + wrow) * INN + k0 + wkq);

        __syncthreads();
#pragma unroll
        for (int i = 0; i < 4; i++) {
            const int c = tid + i * 128;
            const int xr = c >> 3;
            const int xk = (c & 7) * 4;
            Xs[xk + 0][xr] = xa[i].x; Xs[xk + 1][xr] = xa[i].y;
            Xs[xk + 2][xr] = xa[i].z; Xs[xk + 3][xr] = xa[i].w;
        }
        Ws[wkq + 0][wrow] = wa.x; Ws[wkq + 1][wrow] = wa.y;
        Ws[wkq + 2][wrow] = wa.z; Ws[wkq + 3][wrow] = wa.w;
        __syncthreads();

#pragma unroll
        for (int kk = 0; kk < K1KC; kk++) {
            unsigned long long a01 = *(const unsigned long long*)&Xs[kk][ty * 4];
            unsigned long long a23 = *(const unsigned long long*)&Xs[kk][ty * 4 + 2];
            float2 bv = *(const float2*)&Ws[kk][tx * 2];
            unsigned long long bx = dup2_(bv.x);
            unsigned long long by = dup2_(bv.y);
            fma2_(acc00, a01, bx);
            fma2_(acc10, a23, bx);
            fma2_(acc01, a01, by);
            fma2_(acc11, a23, by);
        }
    }

    float b0 = 0.f, b1 = 0.f;
    if (bias) {
        b0 = bias[n0 + tx * 2 + 0];
        b1 = bias[n0 + tx * 2 + 1];
    }

    float2 a00 = unpk_(acc00), a10 = unpk_(acc10);
    float2 a01v = unpk_(acc01), a11 = unpk_(acc11);
    float ra[4][2] = {
        {a00.x, a01v.x}, {a00.y, a01v.y},
        {a10.x, a11.x},  {a10.y, a11.y}
    };

    float* __restrict__ outg = g_gate[g];
#pragma unroll
    for (int i = 0; i < 4; i++) {
        const int m = ty * 4 + i;
        float y0 = ra[i][0] + b0;
        float y1 = ra[i][1] + b1;
        if (g == 3)      { y0 = softplusf_(y0); y1 = softplusf_(y1); }
        else if (g >= 4) { y0 = sigmoidf_(y0);  y1 = sigmoidf_(y1);  }
        *(float2*)(outg + m * HH + n0 + tx * 2) = make_float2(y0, y1);
    }
}

// ----------------------------------------------------------------------------
// Kernel 2: n = f*n_prev + i*k ; m = max(f*m_prev, i) ;
//           denom[b] = max(sum_h n*q, 1) ; vq[b] = sum_h v*q
// ----------------------------------------------------------------------------
__global__ __launch_bounds__(1024) void k2_nm_reduce(
    const float* __restrict__ n_prev, const float* __restrict__ m_prev,
    float* __restrict__ out_n, float* __restrict__ out_m)
{
    const int b = blockIdx.x;
    const int tid = threadIdx.x;
    const int h = b * HH + tid;

    const float qv = g_gate[0][h];
    const float kv = g_gate[1][h];
    const float vv = g_gate[2][h];
    const float iv = g_gate[3][h];
    const float fv = g_gate[4][h];
    const float nv = fmaf(fv, n_prev[h], iv * kv);
    const float mv = fmaxf(fv * m_prev[h], iv);
    out_n[h] = nv;
    out_m[h] = mv;

    float snq = nv * qv;
    float svq = vv * qv;
#pragma unroll
    for (int s = 16; s > 0; s >>= 1) {
        snq += __shfl_xor_sync(0xFFFFFFFFu, snq, s);
        svq += __shfl_xor_sync(0xFFFFFFFFu, svq, s);
    }
    __shared__ float p1[32], p2[32];
    const int warp = tid >> 5, lane = tid & 31;
    if (lane == 0) { p1[warp] = snq; p2[warp] = svq; }
    __syncthreads();
    if (warp == 0) {
        float a = p1[lane], c = p2[lane];
#pragma unroll
        for (int s = 16; s > 0; s >>= 1) {
            a += __shfl_xor_sync(0xFFFFFFFFu, a, s);
            c += __shfl_xor_sync(0xFFFFFFFFu, c, s);
        }
        if (lane == 0) {
            g_denom[b] = fmaxf(a, 1.0f);
            g_vq[b] = c;
        }
    }
}

// ----------------------------------------------------------------------------
// Kernel 3: streaming 512 MB + fused GroupNorm epilogue (last block per batch):
//   C[b,r,c] = f_r * C_prev[b,r,c] + (i_r*k_r) * v_c
//   ht_raw[b,r] = f_r * <C_prev[b,r,:], q> + (i_r*k_r) * vq[b]
//   epilogue: h = o * GroupNorm(ht_raw/denom)
// grid = (64 rowblocks, 64 b), block = 512 (16 warps, 1 warp/row)
// ----------------------------------------------------------------------------
__global__ __launch_bounds__(512) void k3_c_update(
    const float* __restrict__ C_prev, float* __restrict__ out_C,
    const float* __restrict__ gn_w, const float* __restrict__ gn_b,
    float* __restrict__ out_h)
{
    const int b = blockIdx.y;
    const int r0 = blockIdx.x * 16;
    const int tid = threadIdx.x;

    __shared__ float sq[HH];
    __shared__ float sv[HH];
#pragma unroll
    for (int j = 0; j < 2; j++) {
        const int idx = tid + j * 512;
        sq[idx] = g_gate[0][b * HH + idx];
        sv[idx] = g_gate[2][b * HH + idx];
    }
    __syncthreads();

    const int warp = tid >> 5;
    const int lane = tid & 31;
    const int r = r0 + warp;

    const float f  = g_gate[4][b * HH + r];
    const float ik = g_gate[3][b * HH + r] * g_gate[1][b * HH + r];

    const float* __restrict__ cp = C_prev + ((size_t)b * HH + r) * HH;
    float* __restrict__ co = out_C + ((size_t)b * HH + r) * HH;

    // front-batched loads for MLP
    float4 p[8];
#pragma unroll
    for (int j = 0; j < 8; j++)
        p[j] = __ldcs((const float4*)(cp + lane * 4 + j * 128));

    float dot = 0.0f;
#pragma unroll
    for (int j = 0; j < 8; j++) {
        const int c = lane * 4 + j * 128;
        float4 vv = *(const float4*)(sv + c);
        float4 qq = *(const float4*)(sq + c);
        float4 o;
        o.x = fmaf(f, p[j].x, ik * vv.x);
        o.y = fmaf(f, p[j].y, ik * vv.y);
        o.z = fmaf(f, p[j].z, ik * vv.z);
        o.w = fmaf(f, p[j].w, ik * vv.w);
        __stcs((float4*)(co + c), o);
        dot = fmaf(p[j].x, qq.x, dot);
        dot = fmaf(p[j].y, qq.y, dot);
        dot = fmaf(p[j].z, qq.z, dot);
        dot = fmaf(p[j].w, qq.w, dot);
    }
#pragma unroll
    for (int s = 16; s > 0; s >>= 1)
        dot += __shfl_xor_sync(0xFFFFFFFFu, dot, s);
    if (lane == 0) {
        g_ht[b * HH + r] = fmaf(f, dot, ik * g_vq[b]);
        __threadfence();   // release ht (and C writes) device-wide
    }

    // ---- last-block-per-batch GroupNorm epilogue ----
    __syncthreads();
    __shared__ unsigned int s_old;
    if (tid == 0)
        s_old = atomicAdd(&g_cnt[b], 1u);
    __syncthreads();
    if (s_old != 63u) return;

    __threadfence();  // acquire side
    const float inv_d = 1.0f / g_denom[b];

    float xv[2];
    float s = 0.0f, s2 = 0.0f;
#pragma unroll
    for (int j = 0; j < 2; j++) {
        const int h = tid + j * 512;
        const float v = __ldcg(&g_ht[b * HH + h]) * inv_d;
        xv[j] = v;
        s += v;
        s2 = fmaf(v, v, s2);
    }
#pragma unroll
    for (int st = 16; st > 0; st >>= 1) {
        s  += __shfl_xor_sync(0xFFFFFFFFu, s, st);
        s2 += __shfl_xor_sync(0xFFFFFFFFu, s2, st);
    }
    __shared__ float p1[16], p2[16];
    __shared__ float mu_s, rstd_s;
    if (lane == 0) { p1[warp] = s; p2[warp] = s2; }
    __syncthreads();
    if (warp == 0) {
        float a = (lane < 16) ? p1[lane] : 0.0f;
        float c = (lane < 16) ? p2[lane] : 0.0f;
#pragma unroll
        for (int st = 8; st > 0; st >>= 1) {
            a += __shfl_xor_sync(0xFFFFFFFFu, a, st);
            c += __shfl_xor_sync(0xFFFFFFFFu, c, st);
        }
        if (lane == 0) {
            const float mu = a * (1.0f / HH);
            float var = c * (1.0f / HH) - mu * mu;
            var = fmaxf(var, 0.0f);
            mu_s = mu;
            rstd_s = rsqrtf(var + GN_EPS);
        }
    }
    __syncthreads();
    const float mu = mu_s, rstd = rstd_s;

#pragma unroll
    for (int j = 0; j < 2; j++) {
        const int h = tid + j * 512;
        const float norm = fmaf((xv[j] - mu) * rstd, gn_w[h], gn_b[h]);
        out_h[b * HH + h] = g_gate[5][b * HH + h] * norm;
    }
    if (tid == 0) g_cnt[b] = 0u;   // self-reset for next replay
}

// ----------------------------------------------------------------------------
extern "C" void kernel_launch(void* const* d_in, const int* in_sizes, int n_in,
                              void* d_out, int out_size)
{
    const float* x      = (const float*)d_in[0];
    const float* C_prev = (const float*)d_in[1];
    const float* n_prev = (const float*)d_in[2];
    const float* m_prev = (const float*)d_in[3];
    const float* Wq     = (const float*)d_in[4];
    const float* Wk     = (const float*)d_in[5];
    const float* Wv     = (const float*)d_in[6];
    const float* Wi     = (const float*)d_in[7];
    const float* bi     = (const float*)d_in[8];
    const float* Wf     = (const float*)d_in[9];
    const float* bf     = (const float*)d_in[10];
    const float* Wo     = (const float*)d_in[11];
    const float* bo     = (const float*)d_in[12];
    const float* gn_w   = (const float*)d_in[13];
    const float* gn_b   = (const float*)d_in[14];

    float* out   = (float*)d_out;
    float* out_h = out;                                   // [B,H]
    float* out_C = out_h + BB * HH;                       // [B,H,H]
    float* out_n = out_C + (size_t)BB * HH * HH;          // [B,H]
    float* out_m = out_n + BB * HH;                       // [B,H]

    dim3 g1(HH / K1N, 6);
    k1_gemm_gates<<<g1, 128>>>(x, Wq, Wk, Wv, Wi, Wf, Wo, bi, bf, bo);
    k2_nm_reduce<<<BB, 1024>>>(n_prev, m_prev, out_n, out_m);
    dim3 g3(HH / 16, BB);
    k3_c_update<<<g3, 512>>>(C_prev, out_C, gn_w, gn_b, out_h);
}

// round 6
// speedup vs baseline: 1.4752x; 1.2027x over previous
#include <cuda_runtime.h>
#include <math.h>

#define BB 64
#define HH 1024
#define INN 1024
#define GN_EPS 1e-5f

#define SPLITS 8
#define KCH 128       // K per split
#define KC 32         // smem K tile
#define NG (6 * HH)   // 6144 fused gate columns

// Small scratch only (partials live in the out_C output region, overwritten by k3)
__device__ float g_gate[6][BB * HH];          // q,k,v,i,f,o
__device__ float g_ht[BB * HH];
__device__ float g_denom[BB];
__device__ float g_vq[BB];
__device__ unsigned int g_cnt[BB];            // zero-init; self-resetting

__device__ __forceinline__ float sigmoidf_(float x) {
    return 1.0f / (1.0f + expf(-x));
}
__device__ __forceinline__ float softplusf_(float x) {
    return fmaxf(x, 0.0f) + log1pf(expf(-fabsf(x)));
}

// ---- packed f32x2 helpers ----
__device__ __forceinline__ unsigned long long dup2_(float v) {
    unsigned long long r;
    asm("mov.b64 %0, {%1, %1};" : "=l"(r) : "r"(__float_as_uint(v)));
    return r;
}
__device__ __forceinline__ void fma2_(unsigned long long& d,
                                      unsigned long long a,
                                      unsigned long long b) {
    asm("fma.rn.f32x2 %0, %1, %2, %0;" : "+l"(d) : "l"(a), "l"(b));
}
__device__ __forceinline__ float2 unpk_(unsigned long long v) {
    unsigned int lo, hi;
    asm("mov.b64 {%0, %1}, %2;" : "=r"(lo), "=r"(hi) : "l"(v));
    return make_float2(__uint_as_float(lo), __uint_as_float(hi));
}

// ----------------------------------------------------------------------------
// Kernel 1: fused split-K GEMM over all six gates.
// part[sp][b][ng] = sum_{k in split sp} x[b,k] * W_all[ng,k], ng in [0,6144).
// Tile 64m x 64n, K-chunk 128 per split, 128 threads, micro 8m x 4n (f32x2).
// grid = (96 n-blocks, 8 splits). Partials written into out_C scratch region.
// ----------------------------------------------------------------------------
__global__ __launch_bounds__(128) void k1_gemm_gates(
    const float* __restrict__ x,
    const float* __restrict__ Wq, const float* __restrict__ Wk,
    const float* __restrict__ Wv, const float* __restrict__ Wi,
    const float* __restrict__ Wf, const float* __restrict__ Wo,
    float* __restrict__ part)   // [SPLITS][BB][NG]
{
    const int n0g = blockIdx.x * 64;       // global n
    const int g = n0g >> 10;
    const int nloc0 = n0g & 1023;          // row within the gate's W
    const float* __restrict__ W =
        (g == 0) ? Wq : (g == 1) ? Wk : (g == 2) ? Wv : (g == 3) ? Wi : (g == 4) ? Wf : Wo;
    const int k0s = blockIdx.y * KCH;

    __shared__ __align__(16) float Xs[KC][68];   // [k][m], stride 272B (16B mult)
    __shared__ __align__(16) float Ws[KC][68];   // [k][n]

    const int tid = threadIdx.x;
    const int tx = tid & 15;   // n micro-group: 4 cols
    const int ty = tid >> 4;   // m micro-group: 8 rows

    unsigned long long acc[4][4];   // [m-pair][nj]
#pragma unroll
    for (int i = 0; i < 4; i++)
#pragma unroll
        for (int j = 0; j < 4; j++) acc[i][j] = 0ull;

    for (int kc0 = 0; kc0 < KCH; kc0 += KC) {
        const int k0 = k0s + kc0;
        // 64 rows x 8 float4-chunks = 512 chunks, 4 per thread (for each of X, W)
        float4 xa[4], wa[4];
#pragma unroll
        for (int i = 0; i < 4; i++) {
            const int c = tid + i * 128;
            const int r = c >> 3;
            const int kq = (c & 7) * 4;
            xa[i] = *(const float4*)(x + r * INN + k0 + kq);
            wa[i] = *(const float4*)(W + (size_t)(nloc0 + r) * INN + k0 + kq);
        }
        __syncthreads();
#pragma unroll
        for (int i = 0; i < 4; i++) {
            const int c = tid + i * 128;
            const int r = c >> 3;
            const int kq = (c & 7) * 4;
            Xs[kq + 0][r] = xa[i].x; Xs[kq + 1][r] = xa[i].y;
            Xs[kq + 2][r] = xa[i].z; Xs[kq + 3][r] = xa[i].w;
            Ws[kq + 0][r] = wa[i].x; Ws[kq + 1][r] = wa[i].y;
            Ws[kq + 2][r] = wa[i].z; Ws[kq + 3][r] = wa[i].w;
        }
        __syncthreads();

#pragma unroll
        for (int kk = 0; kk < KC; kk++) {
            ulonglong2 A0 = *(const ulonglong2*)&Xs[kk][ty * 8];      // rows 0..3
            ulonglong2 A1 = *(const ulonglong2*)&Xs[kk][ty * 8 + 4];  // rows 4..7
            float4 b = *(const float4*)&Ws[kk][tx * 4];
            unsigned long long bd[4] = {dup2_(b.x), dup2_(b.y), dup2_(b.z), dup2_(b.w)};
#pragma unroll
            for (int j = 0; j < 4; j++) {
                fma2_(acc[0][j], A0.x, bd[j]);
                fma2_(acc[1][j], A0.y, bd[j]);
                fma2_(acc[2][j], A1.x, bd[j]);
                fma2_(acc[3][j], A1.y, bd[j]);
            }
        }
    }

    // store: rows m = ty*8 + (0..7) == batch index, cols n0g + tx*4 ..
    float* __restrict__ po = part + (size_t)blockIdx.y * BB * NG;
#pragma unroll
    for (int mi = 0; mi < 4; mi++) {
        float2 c0 = unpk_(acc[mi][0]);
        float2 c1 = unpk_(acc[mi][1]);
        float2 c2 = unpk_(acc[mi][2]);
        float2 c3 = unpk_(acc[mi][3]);
        const int m0 = ty * 8 + mi * 2;
        *(float4*)(po + (size_t)m0 * NG + n0g + tx * 4) =
            make_float4(c0.x, c1.x, c2.x, c3.x);
        *(float4*)(po + (size_t)(m0 + 1) * NG + n0g + tx * 4) =
            make_float4(c0.y, c1.y, c2.y, c3.y);
    }
}

// ----------------------------------------------------------------------------
// Kernel 2: combine split-K partials (fixed order => deterministic), apply
// bias + activations, store gates; then n/m update + denom/vq reductions.
// grid = 64 (batch), block = 1024.
// ----------------------------------------------------------------------------
__global__ __launch_bounds__(1024) void k2_combine_nm(
    const float* __restrict__ part,
    const float* __restrict__ bi, const float* __restrict__ bf,
    const float* __restrict__ bo,
    const float* __restrict__ n_prev, const float* __restrict__ m_prev,
    float* __restrict__ out_n, float* __restrict__ out_m)
{
    const int b = blockIdx.x;
    const int tid = threadIdx.x;
    const int h = b * HH + tid;

    float y[6];
#pragma unroll
    for (int g = 0; g < 6; g++) {
        float s = 0.0f;
#pragma unroll
        for (int sp = 0; sp < SPLITS; sp++)
            s += part[((size_t)sp * BB + b) * NG + g * HH + tid];
        y[g] = s;
    }

    const float qv = y[0];
    const float kv = y[1];
    const float vv = y[2];
    const float iv = softplusf_(y[3] + bi[tid]);
    const float fv = sigmoidf_(y[4] + bf[tid]);
    const float ov = sigmoidf_(y[5] + bo[tid]);

    g_gate[0][h] = qv;
    g_gate[1][h] = kv;
    g_gate[2][h] = vv;
    g_gate[3][h] = iv;
    g_gate[4][h] = fv;
    g_gate[5][h] = ov;

    const float nv = fmaf(fv, n_prev[h], iv * kv);
    const float mv = fmaxf(fv * m_prev[h], iv);
    out_n[h] = nv;
    out_m[h] = mv;

    float snq = nv * qv;
    float svq = vv * qv;
#pragma unroll
    for (int s = 16; s > 0; s >>= 1) {
        snq += __shfl_xor_sync(0xFFFFFFFFu, snq, s);
        svq += __shfl_xor_sync(0xFFFFFFFFu, svq, s);
    }
    __shared__ float p1[32], p2[32];
    const int warp = tid >> 5, lane = tid & 31;
    if (lane == 0) { p1[warp] = snq; p2[warp] = svq; }
    __syncthreads();
    if (warp == 0) {
        float a = p1[lane], c = p2[lane];
#pragma unroll
        for (int s = 16; s > 0; s >>= 1) {
            a += __shfl_xor_sync(0xFFFFFFFFu, a, s);
            c += __shfl_xor_sync(0xFFFFFFFFu, c, s);
        }
        if (lane == 0) {
            g_denom[b] = fmaxf(a, 1.0f);
            g_vq[b] = c;
        }
    }
}

// ----------------------------------------------------------------------------
// Kernel 3: streaming 512 MB + fused GroupNorm epilogue (last block per batch)
// grid = (64 rowblocks, 64 b), block = 512 (16 warps, 1 warp/row)
// Overwrites ALL of out_C (including the region k1 used as scratch).
// ----------------------------------------------------------------------------
__global__ __launch_bounds__(512) void k3_c_update(
    const float* __restrict__ C_prev, float* __restrict__ out_C,
    const float* __restrict__ gn_w, const float* __restrict__ gn_b,
    float* __restrict__ out_h)
{
    const int b = blockIdx.y;
    const int r0 = blockIdx.x * 16;
    const int tid = threadIdx.x;

    __shared__ float sq[HH];
    __shared__ float sv[HH];
#pragma unroll
    for (int j = 0; j < 2; j++) {
        const int idx = tid + j * 512;
        sq[idx] = g_gate[0][b * HH + idx];
        sv[idx] = g_gate[2][b * HH + idx];
    }
    __syncthreads();

    const int warp = tid >> 5;
    const int lane = tid & 31;
    const int r = r0 + warp;

    const float f  = g_gate[4][b * HH + r];
    const float ik = g_gate[3][b * HH + r] * g_gate[1][b * HH + r];

    const float* __restrict__ cp = C_prev + ((size_t)b * HH + r) * HH;
    float* __restrict__ co = out_C + ((size_t)b * HH + r) * HH;

    float4 p[8];
#pragma unroll
    for (int j = 0; j < 8; j++)
        p[j] = __ldcs((const float4*)(cp + lane * 4 + j * 128));

    float dot = 0.0f;
#pragma unroll
    for (int j = 0; j < 8; j++) {
        const int c = lane * 4 + j * 128;
        float4 vv = *(const float4*)(sv + c);
        float4 qq = *(const float4*)(sq + c);
        float4 o;
        o.x = fmaf(f, p[j].x, ik * vv.x);
        o.y = fmaf(f, p[j].y, ik * vv.y);
        o.z = fmaf(f, p[j].z, ik * vv.z);
        o.w = fmaf(f, p[j].w, ik * vv.w);
        __stcs((float4*)(co + c), o);
        dot = fmaf(p[j].x, qq.x, dot);
        dot = fmaf(p[j].y, qq.y, dot);
        dot = fmaf(p[j].z, qq.z, dot);
        dot = fmaf(p[j].w, qq.w, dot);
    }
#pragma unroll
    for (int s = 16; s > 0; s >>= 1)
        dot += __shfl_xor_sync(0xFFFFFFFFu, dot, s);
    if (lane == 0) {
        g_ht[b * HH + r] = fmaf(f, dot, ik * g_vq[b]);
        __threadfence();
    }

    // ---- last-block-per-batch GroupNorm epilogue ----
    __syncthreads();
    __shared__ unsigned int s_old;
    if (tid == 0)
        s_old = atomicAdd(&g_cnt[b], 1u);
    __syncthreads();
    if (s_old != 63u) return;

    __threadfence();
    const float inv_d = 1.0f / g_denom[b];

    float xv[2];
    float s = 0.0f, s2 = 0.0f;
#pragma unroll
    for (int j = 0; j < 2; j++) {
        const int h = tid + j * 512;
        const float v = __ldcg(&g_ht[b * HH + h]) * inv_d;
        xv[j] = v;
        s += v;
        s2 = fmaf(v, v, s2);
    }
#pragma unroll
    for (int st = 16; st > 0; st >>= 1) {
        s  += __shfl_xor_sync(0xFFFFFFFFu, s, st);
        s2 += __shfl_xor_sync(0xFFFFFFFFu, s2, st);
    }
    __shared__ float p1[16], p2[16];
    __shared__ float mu_s, rstd_s;
    if (lane == 0) { p1[warp] = s; p2[warp] = s2; }
    __syncthreads();
    if (warp == 0) {
        float a = (lane < 16) ? p1[lane] : 0.0f;
        float c = (lane < 16) ? p2[lane] : 0.0f;
#pragma unroll
        for (int st = 8; st > 0; st >>= 1) {
            a += __shfl_xor_sync(0xFFFFFFFFu, a, st);
            c += __shfl_xor_sync(0xFFFFFFFFu, c, st);
        }
        if (lane == 0) {
            const float mu = a * (1.0f / HH);
            float var = c * (1.0f / HH) - mu * mu;
            var = fmaxf(var, 0.0f);
            mu_s = mu;
            rstd_s = rsqrtf(var + GN_EPS);
        }
    }
    __syncthreads();
    const float mu = mu_s, rstd = rstd_s;

#pragma unroll
    for (int j = 0; j < 2; j++) {
        const int h = tid + j * 512;
        const float norm = fmaf((xv[j] - mu) * rstd, gn_w[h], gn_b[h]);
        out_h[b * HH + h] = g_gate[5][b * HH + h] * norm;
    }
    if (tid == 0) g_cnt[b] = 0u;
}

// ----------------------------------------------------------------------------
extern "C" void kernel_launch(void* const* d_in, const int* in_sizes, int n_in,
                              void* d_out, int out_size)
{
    const float* x      = (const float*)d_in[0];
    const float* C_prev = (const float*)d_in[1];
    const float* n_prev = (const float*)d_in[2];
    const float* m_prev = (const float*)d_in[3];
    const float* Wq     = (const float*)d_in[4];
    const float* Wk     = (const float*)d_in[5];
    const float* Wv     = (const float*)d_in[6];
    const float* Wi     = (const float*)d_in[7];
    const float* bi     = (const float*)d_in[8];
    const float* Wf     = (const float*)d_in[9];
    const float* bf     = (const float*)d_in[10];
    const float* Wo     = (const float*)d_in[11];
    const float* bo     = (const float*)d_in[12];
    const float* gn_w   = (const float*)d_in[13];
    const float* gn_b   = (const float*)d_in[14];

    float* out   = (float*)d_out;
    float* out_h = out;                                   // [B,H]
    float* out_C = out_h + BB * HH;                       // [B,H,H]
    float* out_n = out_C + (size_t)BB * HH * HH;          // [B,H]
    float* out_m = out_n + BB * HH;                       // [B,H]

    // Split-K partials live in the front of out_C (12.6 MB of its 256 MB);
    // k3 fully overwrites out_C afterwards, so this is pure scratch reuse.
    float* part = out_C;

    dim3 g1(NG / 64, SPLITS);
    k1_gemm_gates<<<g1, 128>>>(x, Wq, Wk, Wv, Wi, Wf, Wo, part);
    k2_combine_nm<<<BB, 1024>>>(part, bi, bf, bo, n_prev, m_prev, out_n, out_m);
    dim3 g3(HH / 16, BB);
    k3_c_update<<<g3, 512>>>(C_prev, out_C, gn_w, gn_b, out_h);
}